// round 1
// baseline (speedup 1.0000x reference)
#include <cuda_runtime.h>

// Segment mean: x[N,128] fp32, sorted segment_ids[N], lengths[B], B<=16.
// out[b,d] = sum_{i in seg b} x[i,d] / lengths[b]

#define NSEG_MAX 16
#define DIM 128
#define THREADS 256

__device__ float g_sums[NSEG_MAX * DIM];

__global__ void gab_zero_kernel() {
    int i = blockIdx.x * blockDim.x + threadIdx.x;
    if (i < NSEG_MAX * DIM) g_sums[i] = 0.0f;
}

__global__ void __launch_bounds__(THREADS)
gab_accum_kernel(const float4* __restrict__ x,
                 const int* __restrict__ seg,
                 int n_rows, int rows_per_block) {
    __shared__ float s_sums[NSEG_MAX * DIM];
    for (int i = threadIdx.x; i < NSEG_MAX * DIM; i += THREADS) s_sums[i] = 0.0f;
    __syncthreads();

    const int start = blockIdx.x * rows_per_block;
    const int end   = min(start + rows_per_block, n_rows);

    const int tx = threadIdx.x & 31;   // float4 column 0..31
    const int ty = threadIdx.x >> 5;   // row lane 0..7

    float4 acc = make_float4(0.f, 0.f, 0.f, 0.f);
    int cur = -1;

    for (int row = start + ty; row < end; row += 8) {
        int s = __ldg(seg + row);                       // warp-uniform broadcast
        float4 v = __ldg(x + (size_t)row * 32 + tx);    // coalesced 128B/warp
        if (s != cur) {
            if (cur >= 0) {
                int base = cur * DIM + tx * 4;
                atomicAdd(&s_sums[base + 0], acc.x);
                atomicAdd(&s_sums[base + 1], acc.y);
                atomicAdd(&s_sums[base + 2], acc.z);
                atomicAdd(&s_sums[base + 3], acc.w);
            }
            acc = make_float4(0.f, 0.f, 0.f, 0.f);
            cur = s;
        }
        acc.x += v.x; acc.y += v.y; acc.z += v.z; acc.w += v.w;
    }
    if (cur >= 0) {
        int base = cur * DIM + tx * 4;
        atomicAdd(&s_sums[base + 0], acc.x);
        atomicAdd(&s_sums[base + 1], acc.y);
        atomicAdd(&s_sums[base + 2], acc.z);
        atomicAdd(&s_sums[base + 3], acc.w);
    }
    __syncthreads();

    if (start >= end) return;
    // Sorted segment ids: this block only touched segs [s0, s1].
    const int s0 = __ldg(seg + start);
    const int s1 = __ldg(seg + end - 1);
    for (int s = s0; s <= s1; s++) {
        for (int i = threadIdx.x; i < DIM; i += THREADS) {
            float v = s_sums[s * DIM + i];
            if (v != 0.0f) atomicAdd(&g_sums[s * DIM + i], v);
        }
    }
}

__global__ void gab_div_kernel(const int* __restrict__ lengths,
                               float* __restrict__ out, int total, int d) {
    int i = blockIdx.x * blockDim.x + threadIdx.x;
    if (i < total) out[i] = g_sums[i] / (float)__ldg(lengths + i / d);
}

// Generic fallback (unexpected shapes): straight global atomics, slow but correct.
__global__ void gab_generic_kernel(const float* __restrict__ x,
                                   const int* __restrict__ seg,
                                   int n_rows, int d, float* __restrict__ sums) {
    long long i = (long long)blockIdx.x * blockDim.x + threadIdx.x;
    long long total = (long long)n_rows * d;
    if (i < total) {
        int row = (int)(i / d);
        int col = (int)(i - (long long)row * d);
        atomicAdd(&sums[seg[row] * d + col], x[i]);
    }
}
__device__ float g_generic_sums[4096];
__global__ void gab_generic_zero(int total) {
    int i = blockIdx.x * blockDim.x + threadIdx.x;
    if (i < total) g_generic_sums[i] = 0.0f;
}
__global__ void gab_generic_div(const int* __restrict__ lengths,
                                float* __restrict__ out, int total, int d) {
    int i = blockIdx.x * blockDim.x + threadIdx.x;
    if (i < total) out[i] = g_generic_sums[i] / (float)lengths[i / d];
}

extern "C" void kernel_launch(void* const* d_in, const int* in_sizes, int n_in,
                              void* d_out, int out_size) {
    const float* x   = (const float*)d_in[0];
    const int*   seg = (const int*)d_in[1];
    const int*   len = (const int*)d_in[2];
    float*       out = (float*)d_out;

    const int n_rows = in_sizes[1];                 // N
    const int b      = in_sizes[2];                 // B
    const int d      = in_sizes[0] / n_rows;        // D

    if (d == DIM && b <= NSEG_MAX) {
        gab_zero_kernel<<<(NSEG_MAX * DIM + 255) / 256, 256>>>();
        const int grid = 2048;
        const int rows_per_block = (n_rows + grid - 1) / grid;
        gab_accum_kernel<<<grid, THREADS>>>((const float4*)x, seg, n_rows, rows_per_block);
        gab_div_kernel<<<(out_size + 255) / 256, 256>>>(len, out, out_size, d);
    } else {
        gab_generic_zero<<<(out_size + 255) / 256, 256>>>(out_size);
        long long total = (long long)n_rows * d;
        int grid = (int)((total + 255) / 256);
        gab_generic_kernel<<<grid, 256>>>(x, seg, n_rows, d, g_generic_sums);
        gab_generic_div<<<(out_size + 255) / 256, 256>>>(len, out, out_size, d);
    }
}

// round 2
// speedup vs baseline: 1.0359x; 1.0359x over previous
#include <cuda_runtime.h>

// Segment mean: x[N,128] fp32, sorted segment_ids[N], lengths[B], B<=16.
// out[b,d] = sum_{i in seg b} x[i,d] / lengths[b]
// Segment boundaries are derived from `lengths` (prefix sum), so the 4MB
// segment_ids array is never read by the hot kernel.

#define NSEG_MAX 16
#define DIM 128
#define THREADS 256
#define GRID 2048

__device__ float g_sums[NSEG_MAX * DIM];
__device__ int   g_offs[NSEG_MAX + 1];

// One tiny kernel: zero accumulators + prefix-sum lengths into offsets.
__global__ void gab_setup_kernel(const int* __restrict__ len, int b) {
    int i = threadIdx.x;
    for (int j = i; j < NSEG_MAX * DIM; j += blockDim.x) g_sums[j] = 0.0f;
    if (i == 0) {
        int acc = 0;
        g_offs[0] = 0;
        for (int s = 0; s < b; s++) { acc += len[s]; g_offs[s + 1] = acc; }
    }
}

__global__ void __launch_bounds__(THREADS)
gab_accum_kernel(const float4* __restrict__ x, int n_rows, int rows_per_block, int b) {
    __shared__ int   s_offs[NSEG_MAX + 1];
    __shared__ float s_part[8][DIM];

    if (threadIdx.x <= b) s_offs[threadIdx.x] = g_offs[threadIdx.x];
    __syncthreads();

    const int start = blockIdx.x * rows_per_block;
    const int end   = min(start + rows_per_block, n_rows);
    if (start >= end) return;

    const int tx = threadIdx.x & 31;   // float4 column 0..31
    const int ty = threadIdx.x >> 5;   // row lane 0..7

    // first segment overlapping [start, end)
    int s0 = 0;
    while (s0 + 1 < b && s_offs[s0 + 1] <= start) s0++;

    for (int s = s0; s < b && s_offs[s] < end; s++) {
        const int r0 = max(start, s_offs[s]);
        const int r1 = min(end,   s_offs[s + 1]);
        // uniform across the whole block -> safe to __syncthreads below

        float4 a0 = make_float4(0.f, 0.f, 0.f, 0.f);
        float4 a1 = make_float4(0.f, 0.f, 0.f, 0.f);

        int row = r0 + ty;
        // two independent accumulators, 2 rows (16 apart) per iteration
        for (; row + 8 < r1; row += 16) {
            float4 v0 = __ldg(x + (size_t)row * 32 + tx);
            float4 v1 = __ldg(x + (size_t)(row + 8) * 32 + tx);
            a0.x += v0.x; a0.y += v0.y; a0.z += v0.z; a0.w += v0.w;
            a1.x += v1.x; a1.y += v1.y; a1.z += v1.z; a1.w += v1.w;
        }
        if (row < r1) {
            float4 v0 = __ldg(x + (size_t)row * 32 + tx);
            a0.x += v0.x; a0.y += v0.y; a0.z += v0.z; a0.w += v0.w;
        }
        a0.x += a1.x; a0.y += a1.y; a0.z += a1.z; a0.w += a1.w;

        // cross-warp reduction for this segment
        s_part[ty][tx * 4 + 0] = a0.x;
        s_part[ty][tx * 4 + 1] = a0.y;
        s_part[ty][tx * 4 + 2] = a0.z;
        s_part[ty][tx * 4 + 3] = a0.w;
        __syncthreads();

        if (threadIdx.x < DIM) {
            float v = 0.f;
            #pragma unroll
            for (int w = 0; w < 8; w++) v += s_part[w][threadIdx.x];
            if (v != 0.0f) atomicAdd(&g_sums[s * DIM + threadIdx.x], v);
        }
        __syncthreads();
    }
}

__global__ void gab_div_kernel(const int* __restrict__ lengths,
                               float* __restrict__ out, int total, int d) {
    int i = blockIdx.x * blockDim.x + threadIdx.x;
    if (i < total) out[i] = g_sums[i] / (float)__ldg(lengths + i / d);
}

// Generic fallback (unexpected shapes): straight global atomics, slow but correct.
__device__ float g_generic_sums[4096];
__global__ void gab_generic_kernel(const float* __restrict__ x,
                                   const int* __restrict__ seg,
                                   int n_rows, int d, float* __restrict__ sums) {
    long long i = (long long)blockIdx.x * blockDim.x + threadIdx.x;
    long long total = (long long)n_rows * d;
    if (i < total) {
        int row = (int)(i / d);
        int col = (int)(i - (long long)row * d);
        atomicAdd(&sums[seg[row] * d + col], x[i]);
    }
}
__global__ void gab_generic_zero(int total) {
    int i = blockIdx.x * blockDim.x + threadIdx.x;
    if (i < total) g_generic_sums[i] = 0.0f;
}
__global__ void gab_generic_div(const int* __restrict__ lengths,
                                float* __restrict__ out, int total, int d) {
    int i = blockIdx.x * blockDim.x + threadIdx.x;
    if (i < total) out[i] = g_generic_sums[i] / (float)lengths[i / d];
}

extern "C" void kernel_launch(void* const* d_in, const int* in_sizes, int n_in,
                              void* d_out, int out_size) {
    const float* x   = (const float*)d_in[0];
    const int*   seg = (const int*)d_in[1];
    const int*   len = (const int*)d_in[2];
    float*       out = (float*)d_out;

    const int n_rows = in_sizes[1];                 // N
    const int b      = in_sizes[2];                 // B
    const int d      = in_sizes[0] / n_rows;        // D

    if (d == DIM && b <= NSEG_MAX) {
        gab_setup_kernel<<<1, 256>>>(len, b);
        const int rows_per_block = (n_rows + GRID - 1) / GRID;
        gab_accum_kernel<<<GRID, THREADS>>>((const float4*)x, n_rows, rows_per_block, b);
        gab_div_kernel<<<(out_size + 255) / 256, 256>>>(len, out, out_size, d);
    } else {
        gab_generic_zero<<<(out_size + 255) / 256, 256>>>(out_size);
        long long total = (long long)n_rows * d;
        int grid = (int)((total + 255) / 256);
        gab_generic_kernel<<<grid, 256>>>(x, seg, n_rows, d, g_generic_sums);
        gab_generic_div<<<(out_size + 255) / 256, 256>>>(len, out, out_size, d);
    }
}